// round 8
// baseline (speedup 1.0000x reference)
#include <cuda_runtime.h>
#include <cuda_bf16.h>
#include <cstdint>

#define HP 200
#define WPIX 200
#define PIX (HP*WPIX)          // 40000
#define CDIM 256
#define RDIM 1024
#define NNODE 300
#define SLOTCAP 384            // per-label slot capacity (safe for any label dist)
#define NSLOT (3*SLOTCAP)      // 1152
#define NTILE 9                // 3 labels x 3 slot-tiles of 128
#define NWORD (PIX/32)         // 1250
#define WPC 97                 // mask-words per k_masksum CTA (13 splits)

// ---------------- device scratch (static, no allocations) ----------------
__device__ __nv_bfloat16 g_H[(size_t)3*PIX*RDIM];   // hidden activations, bf16
__device__ float    g_S[NSLOT*RDIM];                // masked sums (fp32)
__device__ unsigned g_bitsT[(size_t)NWORD*NSLOT];   // transposed mask bits [word][slot]
__device__ float    g_invcnt[NSLOT];
__device__ int      g_slot_of_node[NNODE];
__device__ int      g_node_of_slot[NSLOT];
__device__ int      g_tile_active[NTILE];
__device__ int      g_maskmode;                     // 0=uint8, 1=int32, 2=float32

// ---------------- K_sniff: classify mask buffer dtype at runtime ----------------
// uint8 0/1 data: 32-bit words look like e.g. 0x00010100 -> neither {0,1} nor {0,1.0f}.
// int32 0/1 data: every word in {0,1}.
// float32 0/1.0 data: every word in {0, 0x3F800000}.
// Scanning 16384 words (64 KB, always within the smallest possible buffer of 12 MB)
// makes misclassification probability ~(1/8)^16384 ~ 0.
__global__ void k_sniff(const unsigned* __restrict__ words) {
    __shared__ int s_not01, s_notf;
    if (threadIdx.x == 0) { s_not01 = 0; s_notf = 0; }
    __syncthreads();
    int a = 0, b = 0;
    for (int i = threadIdx.x; i < 16384; i += 256) {
        unsigned w = words[i];
        if (w > 1u) a++;
        if (w != 0u && w != 0x3F800000u) b++;
    }
    if (a) atomicAdd(&s_not01, a);
    if (b) atomicAdd(&s_notf, b);
    __syncthreads();
    if (threadIdx.x == 0)
        g_maskmode = (s_not01 == 0) ? 1 : ((s_notf == 0) ? 2 : 0);
}

// ---------------- K0a: detect label stride, sort nodes by label into slot groups --
__global__ void k_order(const int* __restrict__ labels) {
    // int64 detection: if labels were widened to int64, every odd int32 half-word
    // is zero. For genuine int32 labels in {0,1,2}, P(all 150 odd entries == 0) ~ 0.
    int oddnz = 0;
    for (int i = 1; i < NNODE; i += 2) oddnz += (labels[i] != 0);
    int stride = (oddnz == 0) ? 2 : 1;

    int cnt[3] = {0, 0, 0};
    for (int s = 0; s < NSLOT; s++) g_node_of_slot[s] = -1;
    for (int n = 0; n < NNODE; n++) {
        int k = labels[n * stride];
        if (k < 0 || k > 2) k = 0;
        int slot = k * SLOTCAP + cnt[k];
        cnt[k]++;
        g_slot_of_node[n] = slot;
        g_node_of_slot[slot] = n;
    }
    for (int t = 0; t < NTILE; t++) {
        int k = t / 3, nt = t % 3;
        g_tile_active[t] = (cnt[k] > nt * 128) ? 1 : 0;
    }
}

// ---------------- K0b: zero S, init out with b2 (per matching label) ----------------
__global__ void k_zero(const float* __restrict__ bp2, const float* __restrict__ bl2,
                       const float* __restrict__ bc2, float* __restrict__ out) {
    int slot = blockIdx.x;
    int k = slot / SLOTCAP;
    const float* b2 = (k == 0) ? bp2 : (k == 1) ? bl2 : bc2;
    int node = g_node_of_slot[slot];
    float4 z = {0.f, 0.f, 0.f, 0.f};
    for (int r = threadIdx.x * 4; r < RDIM; r += blockDim.x * 4) {
        *(float4*)&g_S[(size_t)slot * RDIM + r] = z;
        if (node >= 0) {
            *(float4*)&out[(size_t)node * RDIM + r] = *(const float4*)&b2[r];
        }
    }
}

// ---------------- K0c: build transposed bit-packed masks (dtype-adaptive) ---------
__global__ void k_bits(const void* __restrict__ masks) {
    int w = blockIdx.x;
    int n = threadIdx.x;
    if (n >= NNODE) return;
    int mode = g_maskmode;
    const unsigned char* mu8 = (const unsigned char*)masks;
    const int*           mi  = (const int*)masks;
    const float*         mf  = (const float*)masks;
    unsigned word = 0;
    if (mode == 0) {
        #pragma unroll 8
        for (int b = 0; b < 32; b++) {
            size_t idx = (size_t)(w * 32 + b) * NNODE + n;
            if (mu8[idx] != 0) word |= (1u << b);
        }
    } else if (mode == 1) {
        #pragma unroll 8
        for (int b = 0; b < 32; b++) {
            size_t idx = (size_t)(w * 32 + b) * NNODE + n;
            if (mi[idx] != 0) word |= (1u << b);
        }
    } else {
        #pragma unroll 8
        for (int b = 0; b < 32; b++) {
            size_t idx = (size_t)(w * 32 + b) * NNODE + n;
            if (mf[idx] != 0.0f) word |= (1u << b);
        }
    }
    g_bitsT[(size_t)w * NSLOT + g_slot_of_node[n]] = word;
}

// ---------------- K0d: per-slot counts -> 1/cnt ----------------
__global__ void k_counts() {
    __shared__ int red[128];
    int slot = blockIdx.x, tid = threadIdx.x;
    int c = 0;
    for (int w = tid; w < NWORD; w += 128)
        c += __popc(g_bitsT[(size_t)w * NSLOT + slot]);
    red[tid] = c;
    __syncthreads();
    for (int s = 64; s > 0; s >>= 1) {
        if (tid < s) red[tid] += red[tid + s];
        __syncthreads();
    }
    if (tid == 0) {
        int node = g_node_of_slot[slot];
        g_invcnt[slot] = (node >= 0 && red[0] > 0) ? 1.0f / (float)red[0] : 0.0f;
    }
}

// ---------------- K1: H_k = relu(X^T W1_k + b1_k), store bf16 (scalar fp32) -------
__global__ void __launch_bounds__(256, 2) k_gemm1(
    const float* __restrict__ x,
    const float* __restrict__ W1a, const float* __restrict__ W1b, const float* __restrict__ W1c,
    const float* __restrict__ b1a, const float* __restrict__ b1b, const float* __restrict__ b1c)
{
    int k = blockIdx.z;
    const float* W1 = (k == 0) ? W1a : (k == 1) ? W1b : W1c;
    const float* b1 = (k == 0) ? b1a : (k == 1) ? b1b : b1c;
    int r0 = blockIdx.x * 128;
    int p0 = blockIdx.y * 128;

    __shared__ float As[16][128];  // [c-chunk][pixel]
    __shared__ float Bs[16][128];  // [c-chunk][r]

    int tid = threadIdx.x, tx = tid & 15, ty = tid >> 4;
    float acc[8][8];
    #pragma unroll
    for (int i = 0; i < 8; i++)
        #pragma unroll
        for (int j = 0; j < 8; j++) acc[i][j] = 0.0f;

    for (int c0 = 0; c0 < CDIM; c0 += 16) {
        for (int i = tid; i < 2048; i += 256) {
            int kk = i >> 7, pp = i & 127;
            int p = p0 + pp;
            As[kk][pp] = (p < PIX) ? x[(size_t)(c0 + kk) * PIX + p] : 0.0f;
        }
        for (int i = tid; i < 2048; i += 256) {
            int kk = i >> 7, rr = i & 127;
            Bs[kk][rr] = W1[(size_t)(c0 + kk) * RDIM + r0 + rr];
        }
        __syncthreads();
        #pragma unroll
        for (int kk = 0; kk < 16; kk++) {
            float4 a0 = *(float4*)&As[kk][ty * 8];
            float4 a1 = *(float4*)&As[kk][ty * 8 + 4];
            float4 b0 = *(float4*)&Bs[kk][tx * 8];
            float4 b1v = *(float4*)&Bs[kk][tx * 8 + 4];
            float a[8] = {a0.x, a0.y, a0.z, a0.w, a1.x, a1.y, a1.z, a1.w};
            float b[8] = {b0.x, b0.y, b0.z, b0.w, b1v.x, b1v.y, b1v.z, b1v.w};
            #pragma unroll
            for (int i = 0; i < 8; i++)
                #pragma unroll
                for (int j = 0; j < 8; j++)
                    acc[i][j] = fmaf(a[i], b[j], acc[i][j]);
        }
        __syncthreads();
    }

    float bias[8];
    #pragma unroll
    for (int j = 0; j < 8; j++) bias[j] = b1[r0 + tx * 8 + j];

    #pragma unroll
    for (int i = 0; i < 8; i++) {
        int p = p0 + ty * 8 + i;
        if (p < PIX) {
            __nv_bfloat162 o[4];
            #pragma unroll
            for (int j = 0; j < 4; j++) {
                float lo = fmaxf(acc[i][2 * j]     + bias[2 * j],     0.0f);
                float hi = fmaxf(acc[i][2 * j + 1] + bias[2 * j + 1], 0.0f);
                __nv_bfloat162 t;
                t.x = __float2bfloat16_rn(lo);
                t.y = __float2bfloat16_rn(hi);
                o[j] = t;
            }
            *(uint4*)&g_H[((size_t)k * PIX + p) * RDIM + r0 + tx * 8] = *(uint4*)o;
        }
    }
}

// ---------------- K2: S[slot] += sum over masked pixels of H (scalar fp32) --------
__global__ void __launch_bounds__(256, 2) k_masksum() {
    int t = blockIdx.z;
    if (!g_tile_active[t]) return;
    int k = t / 3, nt = t % 3;
    int slot0 = k * SLOTCAP + nt * 128;
    int r0 = blockIdx.x * 128;
    int w0 = blockIdx.y * WPC;
    int wend = min(NWORD, w0 + WPC);

    __shared__ uint4 HsU[32 * 16];    // 32 pixels x 128 bf16
    __shared__ unsigned BitS[128];

    int tid = threadIdx.x, tr = tid & 15, sn = tid >> 4;
    float acc[8][8];                  // [slot i][r j]
    #pragma unroll
    for (int i = 0; i < 8; i++)
        #pragma unroll
        for (int j = 0; j < 8; j++) acc[i][j] = 0.0f;

    const __nv_bfloat16* Hbase = g_H + (size_t)k * PIX * RDIM + r0;

    for (int w = w0; w < wend; w++) {
        for (int i = tid; i < 512; i += 256) {
            int p = i >> 4, q = i & 15;
            HsU[i] = *(const uint4*)(Hbase + (size_t)(w * 32 + p) * RDIM + q * 8);
        }
        if (tid < 128) BitS[tid] = g_bitsT[(size_t)w * NSLOT + slot0 + tid];
        __syncthreads();

        unsigned myb[8];
        #pragma unroll
        for (int i = 0; i < 8; i++) myb[i] = BitS[sn * 8 + i];

        #pragma unroll 4
        for (int p = 0; p < 32; p++) {
            uint4 hv = HsU[p * 16 + tr];
            __nv_bfloat162* hb = (__nv_bfloat162*)&hv;
            float h[8];
            #pragma unroll
            for (int j = 0; j < 4; j++) {
                float2 f = __bfloat1622float2(hb[j]);
                h[2 * j] = f.x; h[2 * j + 1] = f.y;
            }
            #pragma unroll
            for (int i = 0; i < 8; i++) {
                float m = ((myb[i] >> p) & 1u) ? 1.0f : 0.0f;
                #pragma unroll
                for (int j = 0; j < 8; j++)
                    acc[i][j] = fmaf(m, h[j], acc[i][j]);
            }
        }
        __syncthreads();
    }

    #pragma unroll
    for (int i = 0; i < 8; i++) {
        int slot = slot0 + sn * 8 + i;
        #pragma unroll
        for (int j = 0; j < 8; j++)
            atomicAdd(&g_S[(size_t)slot * RDIM + r0 + tr * 8 + j], acc[i][j]);
    }
}

// ---------------- K3: out[node] += (S/cnt) @ W2_k  (b2 already in out) ------------
__global__ void __launch_bounds__(256) k_out(
    const float* __restrict__ W2a, const float* __restrict__ W2b, const float* __restrict__ W2c,
    float* __restrict__ out)
{
    int t = blockIdx.z;
    if (!g_tile_active[t]) return;
    int k = t / 3;
    int slot0 = k * SLOTCAP + (t % 3) * 128;
    const float* W2 = (k == 0) ? W2a : (k == 1) ? W2b : W2c;
    int r0 = blockIdx.x * 128;
    int c0 = blockIdx.y * 128;   // split-K over the 1024 contraction dim

    __shared__ float As[128][17]; // [slot][c-chunk], padded
    __shared__ float Bs[16][128];

    int tid = threadIdx.x, tx = tid & 15, ty = tid >> 4;
    float acc[8][8];
    #pragma unroll
    for (int i = 0; i < 8; i++)
        #pragma unroll
        for (int j = 0; j < 8; j++) acc[i][j] = 0.0f;

    for (int cc = 0; cc < 128; cc += 16) {
        for (int i = tid; i < 2048; i += 256) {
            int s = i >> 4, kk = i & 15;
            As[s][kk] = g_S[(size_t)(slot0 + s) * RDIM + c0 + cc + kk] * g_invcnt[slot0 + s];
        }
        for (int i = tid; i < 2048; i += 256) {
            int kk = i >> 7, rr = i & 127;
            Bs[kk][rr] = W2[(size_t)(c0 + cc + kk) * RDIM + r0 + rr];
        }
        __syncthreads();
        #pragma unroll
        for (int kk = 0; kk < 16; kk++) {
            float a[8];
            #pragma unroll
            for (int i = 0; i < 8; i++) a[i] = As[ty * 8 + i][kk];
            float4 b0 = *(float4*)&Bs[kk][tx * 8];
            float4 b1 = *(float4*)&Bs[kk][tx * 8 + 4];
            float b[8] = {b0.x, b0.y, b0.z, b0.w, b1.x, b1.y, b1.z, b1.w};
            #pragma unroll
            for (int i = 0; i < 8; i++)
                #pragma unroll
                for (int j = 0; j < 8; j++)
                    acc[i][j] = fmaf(a[i], b[j], acc[i][j]);
        }
        __syncthreads();
    }

    #pragma unroll
    for (int i = 0; i < 8; i++) {
        int slot = slot0 + ty * 8 + i;
        int node = g_node_of_slot[slot];
        if (node >= 0) {
            #pragma unroll
            for (int j = 0; j < 8; j++)
                atomicAdd(&out[(size_t)node * RDIM + r0 + tx * 8 + j], acc[i][j]);
        }
    }
}

// ---------------- launch ----------------
extern "C" void kernel_launch(void* const* d_in, const int* in_sizes, int n_in,
                              void* d_out, int out_size) {
    const float* x      = (const float*)d_in[0];
    const void*  masks  = d_in[1];
    const int*   labels = (const int*)d_in[2];
    const float* Wp1 = (const float*)d_in[3];  const float* bp1 = (const float*)d_in[4];
    const float* Wp2 = (const float*)d_in[5];  const float* bp2 = (const float*)d_in[6];
    const float* Wl1 = (const float*)d_in[7];  const float* bl1 = (const float*)d_in[8];
    const float* Wl2 = (const float*)d_in[9];  const float* bl2 = (const float*)d_in[10];
    const float* Wc1 = (const float*)d_in[11]; const float* bc1 = (const float*)d_in[12];
    const float* Wc2 = (const float*)d_in[13]; const float* bc2 = (const float*)d_in[14];
    float* out = (float*)d_out;

    k_sniff<<<1, 256>>>((const unsigned*)masks);
    k_order<<<1, 1>>>(labels);
    k_zero<<<NSLOT, 256>>>(bp2, bl2, bc2, out);
    k_bits<<<NWORD, 320>>>(masks);
    k_counts<<<NSLOT, 128>>>();
    k_gemm1<<<dim3(8, 313, 3), 256>>>(x, Wp1, Wl1, Wc1, bp1, bl1, bc1);
    k_masksum<<<dim3(8, 13, NTILE), 256>>>();
    k_out<<<dim3(8, 8, NTILE), 256>>>(Wp2, Wl2, Wc2, out);
}

// round 9
// speedup vs baseline: 1.1461x; 1.1461x over previous
#include <cuda_runtime.h>
#include <cuda_bf16.h>
#include <cstdint>

typedef unsigned long long ull;

#define HP 200
#define WPIX 200
#define PIX (HP*WPIX)          // 40000
#define CDIM 256
#define RDIM 1024
#define NNODE 300
#define SLOTCAP 384            // per-label slot capacity (safe for any label dist)
#define NSLOT (3*SLOTCAP)      // 1152
#define NTILE 9                // 3 labels x 3 slot-tiles of 128
#define NWORD (PIX/32)         // 1250
#define WPC 97                 // mask-words per k_masksum CTA (13 splits)

// ---------------- device scratch (static, no allocations) ----------------
__device__ __nv_bfloat16 g_H[(size_t)3*PIX*RDIM];   // hidden activations, bf16
__device__ float    g_S[NSLOT*RDIM];                // masked sums (fp32)
__device__ unsigned g_bitsT[(size_t)NWORD*NSLOT];   // transposed mask bits [word][slot]
__device__ float    g_invcnt[NSLOT];
__device__ int      g_slot_of_node[NNODE];
__device__ int      g_node_of_slot[NSLOT];
__device__ int      g_tile_active[NTILE];
__device__ int      g_maskmode;                     // 0=uint8, 1=int32, 2=float32

// ---------------- f32x2 packed-math helpers ----------------
__device__ __forceinline__ ull pk2(float lo, float hi) {
    ull r;
    asm("mov.b64 %0, {%1, %2};" : "=l"(r) : "r"(__float_as_uint(lo)), "r"(__float_as_uint(hi)));
    return r;
}
__device__ __forceinline__ void upk2(ull v, float& lo, float& hi) {
    unsigned a, b;
    asm("mov.b64 {%0, %1}, %2;" : "=r"(a), "=r"(b) : "l"(v));
    lo = __uint_as_float(a); hi = __uint_as_float(b);
}
__device__ __forceinline__ ull ffma2(ull a, ull b, ull c) {
    ull d;
    asm("fma.rn.f32x2 %0, %1, %2, %3;" : "=l"(d) : "l"(a), "l"(b), "l"(c));
    return d;
}

// ---------------- K_sniff: classify mask buffer dtype at runtime ----------------
__global__ void k_sniff(const unsigned* __restrict__ words) {
    __shared__ int s_not01, s_notf;
    if (threadIdx.x == 0) { s_not01 = 0; s_notf = 0; }
    __syncthreads();
    int a = 0, b = 0;
    for (int i = threadIdx.x; i < 16384; i += 256) {
        unsigned w = words[i];
        if (w > 1u) a++;
        if (w != 0u && w != 0x3F800000u) b++;
    }
    if (a) atomicAdd(&s_not01, a);
    if (b) atomicAdd(&s_notf, b);
    __syncthreads();
    if (threadIdx.x == 0)
        g_maskmode = (s_not01 == 0) ? 1 : ((s_notf == 0) ? 2 : 0);
}

// ---------------- K0a: detect label stride, sort nodes by label into slot groups --
__global__ void k_order(const int* __restrict__ labels) {
    int oddnz = 0;
    for (int i = 1; i < NNODE; i += 2) oddnz += (labels[i] != 0);
    int stride = (oddnz == 0) ? 2 : 1;

    int cnt[3] = {0, 0, 0};
    for (int s = 0; s < NSLOT; s++) g_node_of_slot[s] = -1;
    for (int n = 0; n < NNODE; n++) {
        int k = labels[n * stride];
        if (k < 0 || k > 2) k = 0;
        int slot = k * SLOTCAP + cnt[k];
        cnt[k]++;
        g_slot_of_node[n] = slot;
        g_node_of_slot[slot] = n;
    }
    for (int t = 0; t < NTILE; t++) {
        int k = t / 3, nt = t % 3;
        g_tile_active[t] = (cnt[k] > nt * 128) ? 1 : 0;
    }
}

// ---------------- K0b: zero S, init out with b2 (per matching label) ----------------
__global__ void k_zero(const float* __restrict__ bp2, const float* __restrict__ bl2,
                       const float* __restrict__ bc2, float* __restrict__ out) {
    int slot = blockIdx.x;
    int k = slot / SLOTCAP;
    const float* b2 = (k == 0) ? bp2 : (k == 1) ? bl2 : bc2;
    int node = g_node_of_slot[slot];
    float4 z = {0.f, 0.f, 0.f, 0.f};
    for (int r = threadIdx.x * 4; r < RDIM; r += blockDim.x * 4) {
        *(float4*)&g_S[(size_t)slot * RDIM + r] = z;
        if (node >= 0) {
            *(float4*)&out[(size_t)node * RDIM + r] = *(const float4*)&b2[r];
        }
    }
}

// ---------------- K0c: build transposed bit-packed masks (dtype-adaptive) ---------
__global__ void k_bits(const void* __restrict__ masks) {
    int w = blockIdx.x;
    int n = threadIdx.x;
    if (n >= NNODE) return;
    int mode = g_maskmode;
    const unsigned char* mu8 = (const unsigned char*)masks;
    const int*           mi  = (const int*)masks;
    const float*         mf  = (const float*)masks;
    unsigned word = 0;
    if (mode == 0) {
        #pragma unroll 8
        for (int b = 0; b < 32; b++) {
            size_t idx = (size_t)(w * 32 + b) * NNODE + n;
            if (mu8[idx] != 0) word |= (1u << b);
        }
    } else if (mode == 1) {
        #pragma unroll 8
        for (int b = 0; b < 32; b++) {
            size_t idx = (size_t)(w * 32 + b) * NNODE + n;
            if (mi[idx] != 0) word |= (1u << b);
        }
    } else {
        #pragma unroll 8
        for (int b = 0; b < 32; b++) {
            size_t idx = (size_t)(w * 32 + b) * NNODE + n;
            if (mf[idx] != 0.0f) word |= (1u << b);
        }
    }
    g_bitsT[(size_t)w * NSLOT + g_slot_of_node[n]] = word;
}

// ---------------- K0d: per-slot counts -> 1/cnt ----------------
__global__ void k_counts() {
    __shared__ int red[128];
    int slot = blockIdx.x, tid = threadIdx.x;
    int c = 0;
    for (int w = tid; w < NWORD; w += 128)
        c += __popc(g_bitsT[(size_t)w * NSLOT + slot]);
    red[tid] = c;
    __syncthreads();
    for (int s = 64; s > 0; s >>= 1) {
        if (tid < s) red[tid] += red[tid + s];
        __syncthreads();
    }
    if (tid == 0) {
        int node = g_node_of_slot[slot];
        g_invcnt[slot] = (node >= 0 && red[0] > 0) ? 1.0f / (float)red[0] : 0.0f;
    }
}

// ---------------- K1: H_k = relu(X^T W1_k + b1_k), store bf16 (f32x2) -------------
__global__ void __launch_bounds__(256, 2) k_gemm1(
    const float* __restrict__ x,
    const float* __restrict__ W1a, const float* __restrict__ W1b, const float* __restrict__ W1c,
    const float* __restrict__ b1a, const float* __restrict__ b1b, const float* __restrict__ b1c)
{
    int k = blockIdx.z;
    const float* W1 = (k == 0) ? W1a : (k == 1) ? W1b : W1c;
    const float* b1 = (k == 0) ? b1a : (k == 1) ? b1b : b1c;
    int r0 = blockIdx.x * 128;
    int p0 = blockIdx.y * 128;

    __shared__ float As[16][128];  // [c-chunk][pixel]
    __shared__ float Bs[16][128];  // [c-chunk][r]

    int tid = threadIdx.x, tx = tid & 15, ty = tid >> 4;
    ull acc2[8][4];
    #pragma unroll
    for (int i = 0; i < 8; i++)
        #pragma unroll
        for (int j = 0; j < 4; j++) acc2[i][j] = 0ULL;

    for (int c0 = 0; c0 < CDIM; c0 += 16) {
        for (int i = tid; i < 2048; i += 256) {
            int kk = i >> 7, pp = i & 127;
            int p = p0 + pp;
            As[kk][pp] = (p < PIX) ? x[(size_t)(c0 + kk) * PIX + p] : 0.0f;
        }
        for (int i = tid; i < 2048; i += 256) {
            int kk = i >> 7, rr = i & 127;
            Bs[kk][rr] = W1[(size_t)(c0 + kk) * RDIM + r0 + rr];
        }
        __syncthreads();
        #pragma unroll
        for (int kk = 0; kk < 16; kk++) {
            float4 a0 = *(float4*)&As[kk][ty * 8];
            float4 a1 = *(float4*)&As[kk][ty * 8 + 4];
            ull av[8];
            av[0] = pk2(a0.x, a0.x); av[1] = pk2(a0.y, a0.y);
            av[2] = pk2(a0.z, a0.z); av[3] = pk2(a0.w, a0.w);
            av[4] = pk2(a1.x, a1.x); av[5] = pk2(a1.y, a1.y);
            av[6] = pk2(a1.z, a1.z); av[7] = pk2(a1.w, a1.w);
            ulonglong2 bA = *(ulonglong2*)&Bs[kk][tx * 8];
            ulonglong2 bB = *(ulonglong2*)&Bs[kk][tx * 8 + 4];
            ull bv[4] = {bA.x, bA.y, bB.x, bB.y};
            #pragma unroll
            for (int i = 0; i < 8; i++)
                #pragma unroll
                for (int j = 0; j < 4; j++)
                    acc2[i][j] = ffma2(av[i], bv[j], acc2[i][j]);
        }
        __syncthreads();
    }

    float bias[8];
    #pragma unroll
    for (int j = 0; j < 8; j++) bias[j] = b1[r0 + tx * 8 + j];

    #pragma unroll
    for (int i = 0; i < 8; i++) {
        int p = p0 + ty * 8 + i;
        if (p < PIX) {
            __nv_bfloat162 o[4];
            #pragma unroll
            for (int j = 0; j < 4; j++) {
                float lo, hi;
                upk2(acc2[i][j], lo, hi);
                lo = fmaxf(lo + bias[2 * j],     0.0f);
                hi = fmaxf(hi + bias[2 * j + 1], 0.0f);
                __nv_bfloat162 t;
                t.x = __float2bfloat16_rn(lo);
                t.y = __float2bfloat16_rn(hi);
                o[j] = t;
            }
            *(uint4*)&g_H[((size_t)k * PIX + p) * RDIM + r0 + tx * 8] = *(uint4*)o;
        }
    }
}

// ---------------- K2: S[slot] += sum over masked pixels of H (f32x2) --------------
__global__ void __launch_bounds__(256, 2) k_masksum() {
    int t = blockIdx.z;
    if (!g_tile_active[t]) return;
    int k = t / 3, nt = t % 3;
    int slot0 = k * SLOTCAP + nt * 128;
    int r0 = blockIdx.x * 128;
    int w0 = blockIdx.y * WPC;
    int wend = min(NWORD, w0 + WPC);

    __shared__ uint4 HsU[32 * 16];    // 32 pixels x 128 bf16
    __shared__ unsigned BitS[128];

    int tid = threadIdx.x, tr = tid & 15, sn = tid >> 4;
    ull acc2[8][4];
    #pragma unroll
    for (int i = 0; i < 8; i++)
        #pragma unroll
        for (int j = 0; j < 4; j++) acc2[i][j] = 0ULL;

    const __nv_bfloat16* Hbase = g_H + (size_t)k * PIX * RDIM + r0;

    for (int w = w0; w < wend; w++) {
        for (int i = tid; i < 512; i += 256) {
            int p = i >> 4, q = i & 15;
            HsU[i] = *(const uint4*)(Hbase + (size_t)(w * 32 + p) * RDIM + q * 8);
        }
        if (tid < 128) BitS[tid] = g_bitsT[(size_t)w * NSLOT + slot0 + tid];
        __syncthreads();

        unsigned myb[8];
        #pragma unroll
        for (int i = 0; i < 8; i++) myb[i] = BitS[sn * 8 + i];

        #pragma unroll 8
        for (int p = 0; p < 32; p++) {
            uint4 hv = HsU[p * 16 + tr];
            __nv_bfloat162* hb = (__nv_bfloat162*)&hv;
            ull h2[4];
            #pragma unroll
            for (int j = 0; j < 4; j++) {
                float2 f = __bfloat1622float2(hb[j]);
                h2[j] = pk2(f.x, f.y);
            }
            #pragma unroll
            for (int i = 0; i < 8; i++) {
                ull m2 = ((myb[i] >> p) & 1u) ? 0x3F8000003F800000ULL : 0ULL;
                #pragma unroll
                for (int j = 0; j < 4; j++)
                    acc2[i][j] = ffma2(m2, h2[j], acc2[i][j]);
            }
        }
        __syncthreads();
    }

    #pragma unroll
    for (int i = 0; i < 8; i++) {
        int slot = slot0 + sn * 8 + i;
        #pragma unroll
        for (int j = 0; j < 4; j++) {
            float lo, hi;
            upk2(acc2[i][j], lo, hi);
            atomicAdd(&g_S[(size_t)slot * RDIM + r0 + tr * 8 + 2 * j],     lo);
            atomicAdd(&g_S[(size_t)slot * RDIM + r0 + tr * 8 + 2 * j + 1], hi);
        }
    }
}

// ---------------- K3: out[node] += (S/cnt) @ W2_k  (b2 already in out) ------------
__global__ void __launch_bounds__(256) k_out(
    const float* __restrict__ W2a, const float* __restrict__ W2b, const float* __restrict__ W2c,
    float* __restrict__ out)
{
    int t = blockIdx.z;
    if (!g_tile_active[t]) return;
    int k = t / 3;
    int slot0 = k * SLOTCAP + (t % 3) * 128;
    const float* W2 = (k == 0) ? W2a : (k == 1) ? W2b : W2c;
    int r0 = blockIdx.x * 128;
    int c0 = blockIdx.y * 128;   // split-K over the 1024 contraction dim

    __shared__ float As[128][17]; // [slot][c-chunk], padded
    __shared__ float Bs[16][128];

    int tid = threadIdx.x, tx = tid & 15, ty = tid >> 4;
    float acc[8][8];
    #pragma unroll
    for (int i = 0; i < 8; i++)
        #pragma unroll
        for (int j = 0; j < 8; j++) acc[i][j] = 0.0f;

    for (int cc = 0; cc < 128; cc += 16) {
        for (int i = tid; i < 2048; i += 256) {
            int s = i >> 4, kk = i & 15;
            As[s][kk] = g_S[(size_t)(slot0 + s) * RDIM + c0 + cc + kk] * g_invcnt[slot0 + s];
        }
        for (int i = tid; i < 2048; i += 256) {
            int kk = i >> 7, rr = i & 127;
            Bs[kk][rr] = W2[(size_t)(c0 + cc + kk) * RDIM + r0 + rr];
        }
        __syncthreads();
        #pragma unroll
        for (int kk = 0; kk < 16; kk++) {
            float a[8];
            #pragma unroll
            for (int i = 0; i < 8; i++) a[i] = As[ty * 8 + i][kk];
            float4 b0 = *(float4*)&Bs[kk][tx * 8];
            float4 b1 = *(float4*)&Bs[kk][tx * 8 + 4];
            float b[8] = {b0.x, b0.y, b0.z, b0.w, b1.x, b1.y, b1.z, b1.w};
            #pragma unroll
            for (int i = 0; i < 8; i++)
                #pragma unroll
                for (int j = 0; j < 8; j++)
                    acc[i][j] = fmaf(a[i], b[j], acc[i][j]);
        }
        __syncthreads();
    }

    #pragma unroll
    for (int i = 0; i < 8; i++) {
        int slot = slot0 + ty * 8 + i;
        int node = g_node_of_slot[slot];
        if (node >= 0) {
            #pragma unroll
            for (int j = 0; j < 8; j++)
                atomicAdd(&out[(size_t)node * RDIM + r0 + tx * 8 + j], acc[i][j]);
        }
    }
}

// ---------------- launch ----------------
extern "C" void kernel_launch(void* const* d_in, const int* in_sizes, int n_in,
                              void* d_out, int out_size) {
    const float* x      = (const float*)d_in[0];
    const void*  masks  = d_in[1];
    const int*   labels = (const int*)d_in[2];
    const float* Wp1 = (const float*)d_in[3];  const float* bp1 = (const float*)d_in[4];
    const float* Wp2 = (const float*)d_in[5];  const float* bp2 = (const float*)d_in[6];
    const float* Wl1 = (const float*)d_in[7];  const float* bl1 = (const float*)d_in[8];
    const float* Wl2 = (const float*)d_in[9];  const float* bl2 = (const float*)d_in[10];
    const float* Wc1 = (const float*)d_in[11]; const float* bc1 = (const float*)d_in[12];
    const float* Wc2 = (const float*)d_in[13]; const float* bc2 = (const float*)d_in[14];
    float* out = (float*)d_out;

    k_sniff<<<1, 256>>>((const unsigned*)masks);
    k_order<<<1, 1>>>(labels);
    k_zero<<<NSLOT, 256>>>(bp2, bl2, bc2, out);
    k_bits<<<NWORD, 320>>>(masks);
    k_counts<<<NSLOT, 128>>>();
    k_gemm1<<<dim3(8, 313, 3), 256>>>(x, Wp1, Wl1, Wc1, bp1, bl1, bc1);
    k_masksum<<<dim3(8, 13, NTILE), 256>>>();
    k_out<<<dim3(8, 8, NTILE), 256>>>(Wp2, Wl2, Wc2, out);
}